// round 16
// baseline (speedup 1.0000x reference)
#include <cuda_runtime.h>
#include <cuda_fp16.h>

#define HH 64
#define CC 8
#define LL 96
#define TT 24
#define BB 4096
#define ENB 16   // encoder batches per block (2 blocks/SM)
#define DNB 16   // decoder batches per block

// Scratch (device globals — no allocations allowed)
__device__ __half g_enc_h[(size_t)BB * LL * HH];   // batch-major fp16 enc_out
__device__ float2 g_h0_pk[(BB / 2) * HH];
__device__ float2 g_c0_pk[(BB / 2) * HH];
__device__ __half g_Wf[256 * 128];                 // fused gate weights (Wih @ combW)
__device__ float  g_bias2[256];                    // bih+bhh + Wih@comb_b

__device__ __forceinline__ float tanha(float x) {
    float r; asm("tanh.approx.f32 %0, %1;" : "=f"(r) : "f"(x)); return r;
}
__device__ __forceinline__ float sigt(float x) {
    return fmaf(tanha(x * 0.5f), 0.5f, 0.5f);
}
__device__ __forceinline__ unsigned h2u(float x, float y) {
    __half2 h = __floats2half2_rn(x, y);
    return *reinterpret_cast<unsigned*>(&h);
}
__device__ __forceinline__ unsigned s2u(const void* p) {
    unsigned a;
    asm("{ .reg .u64 t; cvta.to.shared.u64 t, %1; cvt.u32.u64 %0, t; }" : "=r"(a) : "l"(p));
    return a;
}
__device__ __forceinline__ void mma16816(
    float& d0, float& d1, float& d2, float& d3,
    unsigned a0, unsigned a1, unsigned a2, unsigned a3,
    unsigned b0, unsigned b1)
{
    asm volatile(
        "mma.sync.aligned.m16n8k16.row.col.f32.f16.f16.f32 "
        "{%0,%1,%2,%3}, {%4,%5,%6,%7}, {%8,%9}, {%0,%1,%2,%3};"
        : "+f"(d0), "+f"(d1), "+f"(d2), "+f"(d3)
        : "r"(a0), "r"(a1), "r"(a2), "r"(a3), "r"(b0), "r"(b1));
}
__device__ __forceinline__ void ldsm4t(unsigned& a0, unsigned& a1, unsigned& a2, unsigned& a3,
                                       unsigned addr)
{
    asm volatile("ldmatrix.sync.aligned.m8n8.x4.trans.shared.b16 {%0,%1,%2,%3}, [%4];"
                 : "=r"(a0), "=r"(a1), "=r"(a2), "=r"(a3) : "r"(addr));
}

// ---------------------------------------------------------------------------
// Encoder: 16 batches/block, 256 threads, 2 blocks/SM. Also computes a
// 128-entry slice of Wfused = dec_Wih @ comb_W (prep folded in).
// ---------------------------------------------------------------------------
struct __align__(16) EncSmem {
    __half xT[ENB][776];
    __half hT[ENB][72];
    float  sg[256][18];
    float  bias[256];
};

__global__ __launch_bounds__(256, 2) void enc_kernel(
    const float* __restrict__ x_enc,
    const float* __restrict__ Wih, const float* __restrict__ Whh,
    const float* __restrict__ bih, const float* __restrict__ bhh,
    const float* __restrict__ dWih, const float* __restrict__ dcombW,
    const float* __restrict__ dbih, const float* __restrict__ dbhh,
    const float* __restrict__ dcomb_b)
{
    extern __shared__ char smem_raw[];
    EncSmem* s = reinterpret_cast<EncSmem*>(smem_raw);
    const int t = threadIdx.x;
    const int wid = t >> 5, lane = t & 31;
    const int g4 = lane >> 2, tig = lane & 3;
    const size_t b0 = (size_t)blockIdx.x * ENB;
    const int bp0 = blockIdx.x * (ENB / 2);

    // ---- folded prep: this block's 128-entry slice of Wfused ----
    if (t < 128) {
        const int idx = blockIdx.x * 128 + t;
        const int r = idx >> 7, k = idx & 127;
        float acc = 0.f;
#pragma unroll 8
        for (int j = 0; j < 64; j++)
            acc = fmaf(dWih[r * 64 + j], dcombW[j * 128 + k], acc);
        g_Wf[idx] = __float2half_rn(acc);
    }
    if (blockIdx.x == 0) {
        float b = dbih[t] + dbhh[t];
#pragma unroll 8
        for (int j = 0; j < 64; j++)
            b = fmaf(dWih[t * 64 + j], dcomb_b[j], b);
        g_bias2[t] = b;
    }

    unsigned A[2][5][4];
#pragma unroll
    for (int mi = 0; mi < 2; mi++) {
        const int r0 = 16 * (2 * wid + mi) + g4;
#pragma unroll
        for (int kt = 0; kt < 5; kt++) {
            const int c0 = 16 * kt + 2 * tig;
#pragma unroll
            for (int half_ = 0; half_ < 4; half_++) {
                const int rr = r0 + ((half_ & 1) ? 8 : 0);
                const int cc = c0 + ((half_ & 2) ? 8 : 0);
                float w0, w1;
                w0 = (cc < 64) ? Whh[rr * 64 + cc] : ((cc < 72) ? Wih[rr * 8 + cc - 64] : 0.f);
                w1 = (cc + 1 < 64) ? Whh[rr * 64 + cc + 1] : ((cc + 1 < 72) ? Wih[rr * 8 + cc + 1 - 64] : 0.f);
                A[mi][kt][half_] = h2u(w0, w1);
            }
        }
    }
    s->bias[t] = bih[t] + bhh[t];

    for (int i = t; i < ENB * 768; i += 256) {
        int n = i / 768, idx = i % 768, c = idx & 7;
        const float* xb = x_enc + (b0 + n) * 768;
        s->xT[n][idx] = __float2half_rn(xb[idx] - xb[760 + c]);
    }
    for (int i = t; i < ENB * 72; i += 256) ((__half*)s->hT)[i] = __ushort_as_half(0);
    __syncthreads();

    const int jc = t & 63, qc = t >> 6;
    float cs0 = 0.f, cs1 = 0.f, cs2 = 0.f, cs3 = 0.f;
    float h0r = 0.f, h1r = 0.f, h2r = 0.f, h3r = 0.f;

    for (int step = 0; step < LL; step++) {
        float d[2][2][4];
#pragma unroll
        for (int mi = 0; mi < 2; mi++)
#pragma unroll
            for (int nt = 0; nt < 2; nt++) { d[mi][nt][0] = d[mi][nt][1] = d[mi][nt][2] = d[mi][nt][3] = 0.f; }

#pragma unroll
        for (int nt = 0; nt < 2; nt++) {
            const __half* hrow = s->hT[nt * 8 + g4];
            unsigned bh[4][2];
#pragma unroll
            for (int kt = 0; kt < 4; kt++) {
                bh[kt][0] = *(const unsigned*)&hrow[16 * kt + 2 * tig];
                bh[kt][1] = *(const unsigned*)&hrow[16 * kt + 2 * tig + 8];
            }
            unsigned bx = *(const unsigned*)&s->xT[nt * 8 + g4][step * 8 + 2 * tig];
#pragma unroll
            for (int mi = 0; mi < 2; mi++) {
#pragma unroll
                for (int kt = 0; kt < 4; kt++)
                    mma16816(d[mi][nt][0], d[mi][nt][1], d[mi][nt][2], d[mi][nt][3],
                             A[mi][kt][0], A[mi][kt][1], A[mi][kt][2], A[mi][kt][3],
                             bh[kt][0], bh[kt][1]);
                mma16816(d[mi][nt][0], d[mi][nt][1], d[mi][nt][2], d[mi][nt][3],
                         A[mi][4][0], A[mi][4][1], A[mi][4][2], A[mi][4][3], bx, 0u);
            }
        }
#pragma unroll
        for (int mi = 0; mi < 2; mi++) {
            const int r0 = 16 * (2 * wid + mi) + g4;
#pragma unroll
            for (int nt = 0; nt < 2; nt++) {
                const int cidx = nt * 8 + 2 * tig;
                *(float2*)&s->sg[r0][cidx]     = make_float2(d[mi][nt][0], d[mi][nt][1]);
                *(float2*)&s->sg[r0 + 8][cidx] = make_float2(d[mi][nt][2], d[mi][nt][3]);
            }
        }
        __syncthreads();

        {
            float2 giA = *(const float2*)&s->sg[jc][4 * qc];
            float2 giB = *(const float2*)&s->sg[jc][4 * qc + 2];
            float2 gfA = *(const float2*)&s->sg[64 + jc][4 * qc];
            float2 gfB = *(const float2*)&s->sg[64 + jc][4 * qc + 2];
            float2 ggA = *(const float2*)&s->sg[128 + jc][4 * qc];
            float2 ggB = *(const float2*)&s->sg[128 + jc][4 * qc + 2];
            float2 goA = *(const float2*)&s->sg[192 + jc][4 * qc];
            float2 goB = *(const float2*)&s->sg[192 + jc][4 * qc + 2];
            float bi = s->bias[jc], bf = s->bias[64 + jc];
            float bg = s->bias[128 + jc], bo = s->bias[192 + jc];

            float i0 = sigt(giA.x + bi), i1 = sigt(giA.y + bi), i2 = sigt(giB.x + bi), i3 = sigt(giB.y + bi);
            float f0 = sigt(gfA.x + bf), f1 = sigt(gfA.y + bf), f2 = sigt(gfB.x + bf), f3 = sigt(gfB.y + bf);
            float t0 = tanha(ggA.x + bg), t1 = tanha(ggA.y + bg), t2 = tanha(ggB.x + bg), t3 = tanha(ggB.y + bg);
            float o0 = sigt(goA.x + bo), o1 = sigt(goA.y + bo), o2 = sigt(goB.x + bo), o3 = sigt(goB.y + bo);
            cs0 = fmaf(f0, cs0, i0 * t0); cs1 = fmaf(f1, cs1, i1 * t1);
            cs2 = fmaf(f2, cs2, i2 * t2); cs3 = fmaf(f3, cs3, i3 * t3);
            h0r = o0 * tanha(cs0); h1r = o1 * tanha(cs1);
            h2r = o2 * tanha(cs2); h3r = o3 * tanha(cs3);

            s->hT[4 * qc + 0][jc] = __float2half_rn(h0r);
            s->hT[4 * qc + 1][jc] = __float2half_rn(h1r);
            s->hT[4 * qc + 2][jc] = __float2half_rn(h2r);
            s->hT[4 * qc + 3][jc] = __float2half_rn(h3r);
            const size_t eb = (b0 + 4 * qc) * (size_t)(LL * HH) + step * HH + jc;
            g_enc_h[eb]                = __float2half_rn(h0r);
            g_enc_h[eb + LL * HH]      = __float2half_rn(h1r);
            g_enc_h[eb + 2 * LL * HH]  = __float2half_rn(h2r);
            g_enc_h[eb + 3 * LL * HH]  = __float2half_rn(h3r);
        }
        __syncthreads();
    }
    g_h0_pk[(bp0 + 2 * qc) * HH + jc]     = make_float2(h0r, h1r);
    g_h0_pk[(bp0 + 2 * qc + 1) * HH + jc] = make_float2(h2r, h3r);
    g_c0_pk[(bp0 + 2 * qc) * HH + jc]     = make_float2(cs0, cs1);
    g_c0_pk[(bp0 + 2 * qc + 1) * HH + jc] = make_float2(cs2, cs3);
}

// ---------------------------------------------------------------------------
// Decoder: R14 structure + live-range surgery: CD two-pass (D[2][4]),
// A-phase two-pass pred with fused emb accumulation.
// ---------------------------------------------------------------------------
struct __align__(16) DecSmem {
    __half  encS[DNB][LL * HH];   // 196608, XOR-swizzled
    __half  abT[DNB][136];        // [emb (0..63); h (64..127)]
    __half  cbT[DNB][136];        // [emb (0..63); ctx (64..127)]
    __half  awl[LL][18];          // attn logits emb-half [l][n]
    __half  sg[256][18];          // gate pre-acts [row][n]; rows 96..191 host
                                  // attn h-half partials during B/CD
    float   embW[CC][HH];
    float   outW[CC][HH];
    float   biasg[256];           // bias2
    float   attn_bS[LL];
    float   emb_bS[HH];
    float   out_bS[CC];
    float   slast[DNB][8];
};

__global__ __launch_bounds__(512, 1) void dec_kernel(
    const float* __restrict__ x_enc,
    const float* __restrict__ emb_W, const float* __restrict__ emb_b,
    const float* __restrict__ attn_W, const float* __restrict__ attn_b,
    const float* __restrict__ Whh,
    const float* __restrict__ out_W, const float* __restrict__ out_b,
    float* __restrict__ y)
{
    extern __shared__ char smem_raw[];
    DecSmem* s = reinterpret_cast<DecSmem*>(smem_raw);
    const int t = threadIdx.x;
    const int wid = t >> 5, lane = t & 31;
    const int g4 = lane >> 2, tig = lane & 3;
    const int b0 = blockIdx.x * DNB;
    const int bp0 = blockIdx.x * (DNB / 2);

    // ---- A fragments ----
    unsigned Ag[12][4];   // gates: kt<8 = Wfused, kt 8..11 = Whh
    unsigned Ax[4][4];    // attn k-split: warps 0-5 k 0..63, warps 6-11 k 64..127
    {
        const int r0 = 16 * wid + g4;
#pragma unroll
        for (int kt = 0; kt < 8; kt++) {
            const int c0 = 16 * kt + 2 * tig;
#pragma unroll
            for (int h_ = 0; h_ < 4; h_++) {
                const int rr = r0 + ((h_ & 1) ? 8 : 0);
                const int cc = c0 + ((h_ & 2) ? 8 : 0);
                Ag[kt][h_] = *(const unsigned*)&g_Wf[rr * 128 + cc];
            }
        }
#pragma unroll
        for (int kt = 8; kt < 12; kt++) {
            const int c0 = 16 * (kt - 8) + 2 * tig;
#pragma unroll
            for (int h_ = 0; h_ < 4; h_++) {
                const int rr = r0 + ((h_ & 1) ? 8 : 0);
                const int cc = c0 + ((h_ & 2) ? 8 : 0);
                Ag[kt][h_] = h2u(Whh[rr * 64 + cc], Whh[rr * 64 + cc + 1]);
            }
        }
        const int ra = 16 * (wid % 6) + g4;
        const int kbase = (wid >= 6 && wid < 12) ? 64 : 0;
#pragma unroll
        for (int kk = 0; kk < 4; kk++) {
            const int c0 = kbase + 16 * kk + 2 * tig;
#pragma unroll
            for (int h_ = 0; h_ < 4; h_++) {
                const int rr = ra + ((h_ & 1) ? 8 : 0);
                const int cc = c0 + ((h_ & 2) ? 8 : 0);
                Ax[kk][h_] = h2u(attn_W[rr * 128 + cc], attn_W[rr * 128 + cc + 1]);
            }
        }
    }

    // ---- Stage SMEM (enc with XOR swizzle on 16B groups) ----
    {
        const float4* eg = (const float4*)(g_enc_h + (size_t)b0 * (LL * HH));
        float4* es = (float4*)s->encS;
        for (int i = t; i < DNB * LL * 8; i += 512) {
            int nl = i >> 3, g = i & 7;
            int l = nl % LL;
            es[nl * 8 + (g ^ (l & 7))] = eg[i];
        }
    }
    for (int i = t; i < CC * HH; i += 512) {
        int j = i >> 3, k = i & 7;
        s->embW[k][j] = emb_W[i];
        ((float*)s->outW)[i] = out_W[i];
    }
    if (t < 256) s->biasg[t] = g_bias2[t];
    if (t < LL) s->attn_bS[t] = attn_b[t];
    if (t < HH) s->emb_bS[t] = emb_b[t];
    if (t < CC) s->out_bS[t] = out_b[t];
    if (t < DNB * 8) {
        int ba = t >> 3, c = t & 7;
        s->slast[ba][c] = x_enc[(size_t)(b0 + ba) * (LL * CC) + (LL - 1) * CC + c];
    }
    __syncthreads();

    // ---- Per-warp batch state (warp n = batch n) ----
    const int n = wid, j0 = lane, j1 = lane + 32;
    float cst0, cst1, hv0, hv1;
    {
        float2 hA = g_h0_pk[(bp0 + (n >> 1)) * HH + j0];
        float2 hB = g_h0_pk[(bp0 + (n >> 1)) * HH + j1];
        float2 cA = g_c0_pk[(bp0 + (n >> 1)) * HH + j0];
        float2 cB = g_c0_pk[(bp0 + (n >> 1)) * HH + j1];
        hv0 = (n & 1) ? hA.y : hA.x;  hv1 = (n & 1) ? hB.y : hB.x;
        cst0 = (n & 1) ? cA.y : cA.x; cst1 = (n & 1) ? cB.y : cB.x;
    }
    const int kRowOff = (lane & 7) + 8 * ((lane >> 4) & 1);
    const int mHalf   = (lane >> 3) & 1;

    {
        float e0 = fmaxf(s->emb_bS[j0], 0.f), e1 = fmaxf(s->emb_bS[j1], 0.f);
        s->abT[n][j0] = __float2half_rn(e0); s->abT[n][j1] = __float2half_rn(e1);
        s->cbT[n][j0] = __float2half_rn(e0); s->cbT[n][j1] = __float2half_rn(e1);
        s->abT[n][64 + j0] = __float2half_rn(hv0);
        s->abT[n][64 + j1] = __float2half_rn(hv1);
    }
    __syncthreads();

    for (int step = 0; step < TT; step++) {
        // B) attn logits via MMA: 12 warps = 6 m-tiles x 2 K-halves
        if (wid < 12) {
            const int mw = (wid < 6) ? wid : wid - 6;
            const int kb = (wid < 6) ? 0 : 64;
            const __half* br0 = s->abT[g4];
            const __half* br1 = s->abT[8 + g4];
            float dA0 = 0.f, dA1 = 0.f, dA2 = 0.f, dA3 = 0.f;
            float dB0 = 0.f, dB1 = 0.f, dB2 = 0.f, dB3 = 0.f;
#pragma unroll
            for (int kk = 0; kk < 4; kk++) {
                const int ko = kb + 16 * kk + 2 * tig;
                unsigned bf0 = *(const unsigned*)&br0[ko];
                unsigned bf1 = *(const unsigned*)&br0[ko + 8];
                mma16816(dA0, dA1, dA2, dA3, Ax[kk][0], Ax[kk][1], Ax[kk][2], Ax[kk][3], bf0, bf1);
                unsigned cf0 = *(const unsigned*)&br1[ko];
                unsigned cf1 = *(const unsigned*)&br1[ko + 8];
                mma16816(dB0, dB1, dB2, dB3, Ax[kk][0], Ax[kk][1], Ax[kk][2], Ax[kk][3], cf0, cf1);
            }
            const int r0 = 16 * mw + g4;
            if (wid < 6) {
                *(__half2*)&s->awl[r0][2 * tig]         = __floats2half2_rn(dA0, dA1);
                *(__half2*)&s->awl[r0 + 8][2 * tig]     = __floats2half2_rn(dA2, dA3);
                *(__half2*)&s->awl[r0][8 + 2 * tig]     = __floats2half2_rn(dB0, dB1);
                *(__half2*)&s->awl[r0 + 8][8 + 2 * tig] = __floats2half2_rn(dB2, dB3);
            } else {
                *(__half2*)&s->sg[96 + r0][2 * tig]         = __floats2half2_rn(dA0, dA1);
                *(__half2*)&s->sg[96 + r0 + 8][2 * tig]     = __floats2half2_rn(dA2, dA3);
                *(__half2*)&s->sg[96 + r0][8 + 2 * tig]     = __floats2half2_rn(dB0, dB1);
                *(__half2*)&s->sg[96 + r0 + 8][8 + 2 * tig] = __floats2half2_rn(dB2, dB3);
            }
        }
        __syncthreads();

        // CD) exp + ctx MMA (unnormalized), TWO jt-PASSES (live-range relief)
        {
            float z0 = __half2float(s->awl[lane][n])      + __half2float(s->sg[96 + lane][n])      + s->attn_bS[lane];
            float z1 = __half2float(s->awl[lane + 32][n]) + __half2float(s->sg[96 + lane + 32][n]) + s->attn_bS[lane + 32];
            float z2 = __half2float(s->awl[lane + 64][n]) + __half2float(s->sg[96 + lane + 64][n]) + s->attn_bS[lane + 64];
            float e0 = __expf(z0), e1 = __expf(z1), e2 = __expf(z2);

            float sum = e0 + e1 + e2;
#pragma unroll
            for (int o = 16; o; o >>= 1) sum += __shfl_xor_sync(0xffffffffu, sum, o);
            float inv = 1.0f / sum;

            const __half* er = s->encS[n];
#pragma unroll
            for (int pass = 0; pass < 2; pass++) {
                float D[2][4];
                D[0][0] = D[0][1] = D[0][2] = D[0][3] = 0.f;
                D[1][0] = D[1][1] = D[1][2] = D[1][3] = 0.f;
#pragma unroll
                for (int kt = 0; kt < 6; kt++) {
                    float wsrc = (kt < 2) ? e0 : (kt < 4) ? e1 : e2;
                    int sb = (kt & 1) * 16 + 2 * tig;
                    float vA = __shfl_sync(0xffffffffu, wsrc, sb);
                    float vB = __shfl_sync(0xffffffffu, wsrc, sb + 1);
                    float vC = __shfl_sync(0xffffffffu, wsrc, sb + 8);
                    float vD = __shfl_sync(0xffffffffu, wsrc, sb + 9);
                    unsigned bf0 = (g4 == 0) ? h2u(vA, vB) : 0u;
                    unsigned bf1 = (g4 == 0) ? h2u(vC, vD) : 0u;
                    const int kRow = 16 * kt + kRowOff;
#pragma unroll
                    for (int jj = 0; jj < 2; jj++) {
                        const int jt = 2 * pass + jj;
                        const int mGroup = 2 * jt + mHalf;
                        unsigned addr = s2u(&er[kRow * HH + ((mGroup ^ (kRow & 7)) << 3)]);
                        unsigned a0, a1, a2, a3;
                        ldsm4t(a0, a1, a2, a3, addr);
                        mma16816(D[jj][0], D[jj][1], D[jj][2], D[jj][3],
                                 a0, a1, a2, a3, bf0, bf1);
                    }
                }
                if (tig == 0) {
#pragma unroll
                    for (int jj = 0; jj < 2; jj++) {
                        const int jt = 2 * pass + jj;
                        s->cbT[n][64 + 16 * jt + g4]     = __float2half_rn(D[jj][0] * inv);
                        s->cbT[n][64 + 16 * jt + g4 + 8] = __float2half_rn(D[jj][2] * inv);
                    }
                }
            }
        }
        __syncthreads();

        // F) fused gates: 8 kt from cbT=[emb;ctx] via Wfused + 4 kt from abT-h via Whh
        {
            const __half* cb0p = s->cbT[g4];
            const __half* cb1p = s->cbT[8 + g4];
            const __half* ab0p = s->abT[g4];
            const __half* ab1p = s->abT[8 + g4];
            float gd0[4] = {0, 0, 0, 0}, gd1[4] = {0, 0, 0, 0};
#pragma unroll
            for (int kt = 0; kt < 8; kt++) {
                unsigned a0f = *(const unsigned*)&cb0p[16 * kt + 2 * tig];
                unsigned a1f = *(const unsigned*)&cb0p[16 * kt + 2 * tig + 8];
                mma16816(gd0[0], gd0[1], gd0[2], gd0[3], Ag[kt][0], Ag[kt][1], Ag[kt][2], Ag[kt][3], a0f, a1f);
                unsigned b0f = *(const unsigned*)&cb1p[16 * kt + 2 * tig];
                unsigned b1f = *(const unsigned*)&cb1p[16 * kt + 2 * tig + 8];
                mma16816(gd1[0], gd1[1], gd1[2], gd1[3], Ag[kt][0], Ag[kt][1], Ag[kt][2], Ag[kt][3], b0f, b1f);
            }
#pragma unroll
            for (int kt = 8; kt < 12; kt++) {
                const int co = 64 + 16 * (kt - 8) + 2 * tig;
                unsigned a0f = *(const unsigned*)&ab0p[co];
                unsigned a1f = *(const unsigned*)&ab0p[co + 8];
                mma16816(gd0[0], gd0[1], gd0[2], gd0[3], Ag[kt][0], Ag[kt][1], Ag[kt][2], Ag[kt][3], a0f, a1f);
                unsigned b0f = *(const unsigned*)&ab1p[co];
                unsigned b1f = *(const unsigned*)&ab1p[co + 8];
                mma16816(gd1[0], gd1[1], gd1[2], gd1[3], Ag[kt][0], Ag[kt][1], Ag[kt][2], Ag[kt][3], b0f, b1f);
            }
            const int r0 = 16 * wid + g4;
            *(__half2*)&s->sg[r0][2 * tig]         = __floats2half2_rn(gd0[0], gd0[1]);
            *(__half2*)&s->sg[r0 + 8][2 * tig]     = __floats2half2_rn(gd0[2], gd0[3]);
            *(__half2*)&s->sg[r0][8 + 2 * tig]     = __floats2half2_rn(gd1[0], gd1[1]);
            *(__half2*)&s->sg[r0 + 8][8 + 2 * tig] = __floats2half2_rn(gd1[2], gd1[3]);
        }
        __syncthreads();

        // A) cell + pred + y + next emb (warp n = batch n), two-pass pred
        {
            float gi0 = __half2float(s->sg[j0][n])       + s->biasg[j0];
            float gi1 = __half2float(s->sg[j1][n])       + s->biasg[j1];
            float gf0 = __half2float(s->sg[64 + j0][n])  + s->biasg[64 + j0];
            float gf1 = __half2float(s->sg[64 + j1][n])  + s->biasg[64 + j1];
            float gg0 = __half2float(s->sg[128 + j0][n]) + s->biasg[128 + j0];
            float gg1 = __half2float(s->sg[128 + j1][n]) + s->biasg[128 + j1];
            float go0 = __half2float(s->sg[192 + j0][n]) + s->biasg[192 + j0];
            float go1 = __half2float(s->sg[192 + j1][n]) + s->biasg[192 + j1];
            float i0 = sigt(gi0), i1 = sigt(gi1);
            float f0 = sigt(gf0), f1 = sigt(gf1);
            float tg0 = tanha(gg0), tg1 = tanha(gg1);
            float o0 = sigt(go0), o1 = sigt(go1);
            cst0 = fmaf(f0, cst0, i0 * tg0);
            cst1 = fmaf(f1, cst1, i1 * tg1);
            hv0 = o0 * tanha(cst0);
            hv1 = o1 * tanha(cst1);

            float* yp = y + ((size_t)(b0 + n) * TT + step) * CC;
            float e0 = s->emb_bS[j0], e1 = s->emb_bS[j1];
#pragma unroll
            for (int pass = 0; pass < 2; pass++) {
                float pc[4];
#pragma unroll
                for (int c = 0; c < 4; c++) {
                    const int cc = 4 * pass + c;
                    pc[c] = fmaf(s->outW[cc][j0], hv0, s->outW[cc][j1] * hv1);
                }
#pragma unroll
                for (int o = 16; o; o >>= 1) {
#pragma unroll
                    for (int c = 0; c < 4; c++) pc[c] += __shfl_xor_sync(0xffffffffu, pc[c], o);
                }
#pragma unroll
                for (int c = 0; c < 4; c++) pc[c] += s->out_bS[4 * pass + c];

                if (lane == 0) {
                    const float* sl = &s->slast[n][4 * pass];
                    *(float4*)(yp + 4 * pass) = make_float4(pc[0] + sl[0], pc[1] + sl[1],
                                                            pc[2] + sl[2], pc[3] + sl[3]);
                }
#pragma unroll
                for (int c = 0; c < 4; c++) {
                    const int cc = 4 * pass + c;
                    e0 = fmaf(s->embW[cc][j0], pc[c], e0);
                    e1 = fmaf(s->embW[cc][j1], pc[c], e1);
                }
            }
            e0 = fmaxf(e0, 0.f); e1 = fmaxf(e1, 0.f);
            s->abT[n][j0] = __float2half_rn(e0); s->abT[n][j1] = __float2half_rn(e1);
            s->cbT[n][j0] = __float2half_rn(e0); s->cbT[n][j1] = __float2half_rn(e1);
            s->abT[n][64 + j0] = __float2half_rn(hv0);
            s->abT[n][64 + j1] = __float2half_rn(hv1);
        }
        __syncthreads();
    }
}

extern "C" void kernel_launch(void* const* d_in, const int* in_sizes, int n_in,
                              void* d_out, int out_size)
{
    const float* x_enc   = (const float*)d_in[0];
    const float* enc_Wih = (const float*)d_in[4];
    const float* enc_Whh = (const float*)d_in[5];
    const float* enc_bih = (const float*)d_in[6];
    const float* enc_bhh = (const float*)d_in[7];
    const float* emb_W   = (const float*)d_in[8];
    const float* emb_b   = (const float*)d_in[9];
    const float* attn_W  = (const float*)d_in[10];
    const float* attn_b  = (const float*)d_in[11];
    const float* comb_W  = (const float*)d_in[12];
    const float* comb_b  = (const float*)d_in[13];
    const float* dec_Wih = (const float*)d_in[14];
    const float* dec_Whh = (const float*)d_in[15];
    const float* dec_bih = (const float*)d_in[16];
    const float* dec_bhh = (const float*)d_in[17];
    const float* out_W   = (const float*)d_in[18];
    const float* out_b   = (const float*)d_in[19];
    float* y = (float*)d_out;

    cudaFuncSetAttribute(enc_kernel, cudaFuncAttributeMaxDynamicSharedMemorySize,
                         (int)sizeof(EncSmem));
    cudaFuncSetAttribute(dec_kernel, cudaFuncAttributeMaxDynamicSharedMemorySize,
                         (int)sizeof(DecSmem));

    enc_kernel<<<BB / ENB, 256, sizeof(EncSmem)>>>(x_enc, enc_Wih, enc_Whh, enc_bih, enc_bhh,
                                                   dec_Wih, comb_W, dec_bih, dec_bhh, comb_b);
    dec_kernel<<<BB / DNB, 512, sizeof(DecSmem)>>>(x_enc, emb_W, emb_b, attn_W, attn_b,
                                                   dec_Whh, out_W, out_b, y);
}

// round 17
// speedup vs baseline: 1.0432x; 1.0432x over previous
#include <cuda_runtime.h>
#include <cuda_fp16.h>

#define HH 64
#define CC 8
#define LL 96
#define TT 24
#define BB 4096
#define ENB 16   // encoder batches per block (2 blocks/SM)
#define DNB 16   // decoder batches per block

// Scratch (device globals — no allocations allowed)
__device__ __half g_enc_h[(size_t)BB * LL * HH];   // batch-major fp16 enc_out
__device__ float2 g_h0_pk[(BB / 2) * HH];
__device__ float2 g_c0_pk[(BB / 2) * HH];
__device__ __half g_Wf[256 * 128];                 // fused gate weights (Wih @ combW)
__device__ float  g_bias2[256];                    // bih+bhh + Wih@comb_b

__device__ __forceinline__ float tanha(float x) {
    float r; asm("tanh.approx.f32 %0, %1;" : "=f"(r) : "f"(x)); return r;
}
__device__ __forceinline__ float sigt(float x) {
    return fmaf(tanha(x * 0.5f), 0.5f, 0.5f);
}
__device__ __forceinline__ unsigned h2u(float x, float y) {
    __half2 h = __floats2half2_rn(x, y);
    return *reinterpret_cast<unsigned*>(&h);
}
__device__ __forceinline__ unsigned s2u(const void* p) {
    unsigned a;
    asm("{ .reg .u64 t; cvta.to.shared.u64 t, %1; cvt.u32.u64 %0, t; }" : "=r"(a) : "l"(p));
    return a;
}
__device__ __forceinline__ void mma16816(
    float& d0, float& d1, float& d2, float& d3,
    unsigned a0, unsigned a1, unsigned a2, unsigned a3,
    unsigned b0, unsigned b1)
{
    asm volatile(
        "mma.sync.aligned.m16n8k16.row.col.f32.f16.f16.f32 "
        "{%0,%1,%2,%3}, {%4,%5,%6,%7}, {%8,%9}, {%0,%1,%2,%3};"
        : "+f"(d0), "+f"(d1), "+f"(d2), "+f"(d3)
        : "r"(a0), "r"(a1), "r"(a2), "r"(a3), "r"(b0), "r"(b1));
}
__device__ __forceinline__ void ldsm4t(unsigned& a0, unsigned& a1, unsigned& a2, unsigned& a3,
                                       unsigned addr)
{
    asm volatile("ldmatrix.sync.aligned.m8n8.x4.trans.shared.b16 {%0,%1,%2,%3}, [%4];"
                 : "=r"(a0), "=r"(a1), "=r"(a2), "=r"(a3) : "r"(addr));
}

// ---------------------------------------------------------------------------
// Encoder: 16 batches/block, 256 threads, 2 blocks/SM. Also computes a
// 128-entry slice of Wfused = dec_Wih @ comb_W (prep folded in).
// ---------------------------------------------------------------------------
struct __align__(16) EncSmem {
    __half xT[ENB][776];
    __half hT[ENB][72];
    float  sg[256][18];
    float  bias[256];
};

__global__ __launch_bounds__(256, 2) void enc_kernel(
    const float* __restrict__ x_enc,
    const float* __restrict__ Wih, const float* __restrict__ Whh,
    const float* __restrict__ bih, const float* __restrict__ bhh,
    const float* __restrict__ dWih, const float* __restrict__ dcombW,
    const float* __restrict__ dbih, const float* __restrict__ dbhh,
    const float* __restrict__ dcomb_b)
{
    extern __shared__ char smem_raw[];
    EncSmem* s = reinterpret_cast<EncSmem*>(smem_raw);
    const int t = threadIdx.x;
    const int wid = t >> 5, lane = t & 31;
    const int g4 = lane >> 2, tig = lane & 3;
    const size_t b0 = (size_t)blockIdx.x * ENB;
    const int bp0 = blockIdx.x * (ENB / 2);

    // ---- folded prep: this block's 128-entry slice of Wfused ----
    if (t < 128) {
        const int idx = blockIdx.x * 128 + t;
        const int r = idx >> 7, k = idx & 127;
        float acc = 0.f;
#pragma unroll 8
        for (int j = 0; j < 64; j++)
            acc = fmaf(dWih[r * 64 + j], dcombW[j * 128 + k], acc);
        g_Wf[idx] = __float2half_rn(acc);
    }
    if (blockIdx.x == 0) {
        float b = dbih[t] + dbhh[t];
#pragma unroll 8
        for (int j = 0; j < 64; j++)
            b = fmaf(dWih[t * 64 + j], dcomb_b[j], b);
        g_bias2[t] = b;
    }

    unsigned A[2][5][4];
#pragma unroll
    for (int mi = 0; mi < 2; mi++) {
        const int r0 = 16 * (2 * wid + mi) + g4;
#pragma unroll
        for (int kt = 0; kt < 5; kt++) {
            const int c0 = 16 * kt + 2 * tig;
#pragma unroll
            for (int half_ = 0; half_ < 4; half_++) {
                const int rr = r0 + ((half_ & 1) ? 8 : 0);
                const int cc = c0 + ((half_ & 2) ? 8 : 0);
                float w0, w1;
                w0 = (cc < 64) ? Whh[rr * 64 + cc] : ((cc < 72) ? Wih[rr * 8 + cc - 64] : 0.f);
                w1 = (cc + 1 < 64) ? Whh[rr * 64 + cc + 1] : ((cc + 1 < 72) ? Wih[rr * 8 + cc + 1 - 64] : 0.f);
                A[mi][kt][half_] = h2u(w0, w1);
            }
        }
    }
    s->bias[t] = bih[t] + bhh[t];

    for (int i = t; i < ENB * 768; i += 256) {
        int n = i / 768, idx = i % 768, c = idx & 7;
        const float* xb = x_enc + (b0 + n) * 768;
        s->xT[n][idx] = __float2half_rn(xb[idx] - xb[760 + c]);
    }
    for (int i = t; i < ENB * 72; i += 256) ((__half*)s->hT)[i] = __ushort_as_half(0);
    __syncthreads();

    const int jc = t & 63, qc = t >> 6;
    float cs0 = 0.f, cs1 = 0.f, cs2 = 0.f, cs3 = 0.f;
    float h0r = 0.f, h1r = 0.f, h2r = 0.f, h3r = 0.f;

    for (int step = 0; step < LL; step++) {
        float d[2][2][4];
#pragma unroll
        for (int mi = 0; mi < 2; mi++)
#pragma unroll
            for (int nt = 0; nt < 2; nt++) { d[mi][nt][0] = d[mi][nt][1] = d[mi][nt][2] = d[mi][nt][3] = 0.f; }

#pragma unroll
        for (int nt = 0; nt < 2; nt++) {
            const __half* hrow = s->hT[nt * 8 + g4];
            unsigned bh[4][2];
#pragma unroll
            for (int kt = 0; kt < 4; kt++) {
                bh[kt][0] = *(const unsigned*)&hrow[16 * kt + 2 * tig];
                bh[kt][1] = *(const unsigned*)&hrow[16 * kt + 2 * tig + 8];
            }
            unsigned bx = *(const unsigned*)&s->xT[nt * 8 + g4][step * 8 + 2 * tig];
#pragma unroll
            for (int mi = 0; mi < 2; mi++) {
#pragma unroll
                for (int kt = 0; kt < 4; kt++)
                    mma16816(d[mi][nt][0], d[mi][nt][1], d[mi][nt][2], d[mi][nt][3],
                             A[mi][kt][0], A[mi][kt][1], A[mi][kt][2], A[mi][kt][3],
                             bh[kt][0], bh[kt][1]);
                mma16816(d[mi][nt][0], d[mi][nt][1], d[mi][nt][2], d[mi][nt][3],
                         A[mi][4][0], A[mi][4][1], A[mi][4][2], A[mi][4][3], bx, 0u);
            }
        }
#pragma unroll
        for (int mi = 0; mi < 2; mi++) {
            const int r0 = 16 * (2 * wid + mi) + g4;
#pragma unroll
            for (int nt = 0; nt < 2; nt++) {
                const int cidx = nt * 8 + 2 * tig;
                *(float2*)&s->sg[r0][cidx]     = make_float2(d[mi][nt][0], d[mi][nt][1]);
                *(float2*)&s->sg[r0 + 8][cidx] = make_float2(d[mi][nt][2], d[mi][nt][3]);
            }
        }
        __syncthreads();

        {
            float2 giA = *(const float2*)&s->sg[jc][4 * qc];
            float2 giB = *(const float2*)&s->sg[jc][4 * qc + 2];
            float2 gfA = *(const float2*)&s->sg[64 + jc][4 * qc];
            float2 gfB = *(const float2*)&s->sg[64 + jc][4 * qc + 2];
            float2 ggA = *(const float2*)&s->sg[128 + jc][4 * qc];
            float2 ggB = *(const float2*)&s->sg[128 + jc][4 * qc + 2];
            float2 goA = *(const float2*)&s->sg[192 + jc][4 * qc];
            float2 goB = *(const float2*)&s->sg[192 + jc][4 * qc + 2];
            float bi = s->bias[jc], bf = s->bias[64 + jc];
            float bg = s->bias[128 + jc], bo = s->bias[192 + jc];

            float i0 = sigt(giA.x + bi), i1 = sigt(giA.y + bi), i2 = sigt(giB.x + bi), i3 = sigt(giB.y + bi);
            float f0 = sigt(gfA.x + bf), f1 = sigt(gfA.y + bf), f2 = sigt(gfB.x + bf), f3 = sigt(gfB.y + bf);
            float t0 = tanha(ggA.x + bg), t1 = tanha(ggA.y + bg), t2 = tanha(ggB.x + bg), t3 = tanha(ggB.y + bg);
            float o0 = sigt(goA.x + bo), o1 = sigt(goA.y + bo), o2 = sigt(goB.x + bo), o3 = sigt(goB.y + bo);
            cs0 = fmaf(f0, cs0, i0 * t0); cs1 = fmaf(f1, cs1, i1 * t1);
            cs2 = fmaf(f2, cs2, i2 * t2); cs3 = fmaf(f3, cs3, i3 * t3);
            h0r = o0 * tanha(cs0); h1r = o1 * tanha(cs1);
            h2r = o2 * tanha(cs2); h3r = o3 * tanha(cs3);

            s->hT[4 * qc + 0][jc] = __float2half_rn(h0r);
            s->hT[4 * qc + 1][jc] = __float2half_rn(h1r);
            s->hT[4 * qc + 2][jc] = __float2half_rn(h2r);
            s->hT[4 * qc + 3][jc] = __float2half_rn(h3r);
            const size_t eb = (b0 + 4 * qc) * (size_t)(LL * HH) + step * HH + jc;
            g_enc_h[eb]                = __float2half_rn(h0r);
            g_enc_h[eb + LL * HH]      = __float2half_rn(h1r);
            g_enc_h[eb + 2 * LL * HH]  = __float2half_rn(h2r);
            g_enc_h[eb + 3 * LL * HH]  = __float2half_rn(h3r);
        }
        __syncthreads();
    }
    g_h0_pk[(bp0 + 2 * qc) * HH + jc]     = make_float2(h0r, h1r);
    g_h0_pk[(bp0 + 2 * qc + 1) * HH + jc] = make_float2(h2r, h3r);
    g_c0_pk[(bp0 + 2 * qc) * HH + jc]     = make_float2(cs0, cs1);
    g_c0_pk[(bp0 + 2 * qc + 1) * HH + jc] = make_float2(cs2, cs3);
}

// ---------------------------------------------------------------------------
// Decoder: R14 structure (measured best): k-split attn A-frags (16 regs),
// single-pass CD with 16 accumulators, sum-reduce overlapping MMA drain.
// ---------------------------------------------------------------------------
struct __align__(16) DecSmem {
    __half  encS[DNB][LL * HH];   // 196608, XOR-swizzled
    __half  abT[DNB][136];        // [emb (0..63); h (64..127)]
    __half  cbT[DNB][136];        // [emb (0..63); ctx (64..127)]
    __half  awl[LL][18];          // attn logits emb-half [l][n]
    __half  sg[256][18];          // gate pre-acts [row][n]; rows 96..191 host
                                  // attn h-half partials during B/CD
    float   embW[CC][HH];
    float   outW[CC][HH];
    float   biasg[256];           // bias2
    float   attn_bS[LL];
    float   emb_bS[HH];
    float   out_bS[CC];
    float   slast[DNB][8];
};

__global__ __launch_bounds__(512, 1) void dec_kernel(
    const float* __restrict__ x_enc,
    const float* __restrict__ emb_W, const float* __restrict__ emb_b,
    const float* __restrict__ attn_W, const float* __restrict__ attn_b,
    const float* __restrict__ Whh,
    const float* __restrict__ out_W, const float* __restrict__ out_b,
    float* __restrict__ y)
{
    extern __shared__ char smem_raw[];
    DecSmem* s = reinterpret_cast<DecSmem*>(smem_raw);
    const int t = threadIdx.x;
    const int wid = t >> 5, lane = t & 31;
    const int g4 = lane >> 2, tig = lane & 3;
    const int b0 = blockIdx.x * DNB;
    const int bp0 = blockIdx.x * (DNB / 2);

    // ---- A fragments ----
    unsigned Ag[12][4];   // gates: kt<8 = Wfused, kt 8..11 = Whh
    unsigned Ax[4][4];    // attn k-split: warps 0-5 k 0..63, warps 6-11 k 64..127
    {
        const int r0 = 16 * wid + g4;
#pragma unroll
        for (int kt = 0; kt < 8; kt++) {
            const int c0 = 16 * kt + 2 * tig;
#pragma unroll
            for (int h_ = 0; h_ < 4; h_++) {
                const int rr = r0 + ((h_ & 1) ? 8 : 0);
                const int cc = c0 + ((h_ & 2) ? 8 : 0);
                Ag[kt][h_] = *(const unsigned*)&g_Wf[rr * 128 + cc];
            }
        }
#pragma unroll
        for (int kt = 8; kt < 12; kt++) {
            const int c0 = 16 * (kt - 8) + 2 * tig;
#pragma unroll
            for (int h_ = 0; h_ < 4; h_++) {
                const int rr = r0 + ((h_ & 1) ? 8 : 0);
                const int cc = c0 + ((h_ & 2) ? 8 : 0);
                Ag[kt][h_] = h2u(Whh[rr * 64 + cc], Whh[rr * 64 + cc + 1]);
            }
        }
        const int ra = 16 * (wid % 6) + g4;
        const int kbase = (wid >= 6 && wid < 12) ? 64 : 0;
#pragma unroll
        for (int kk = 0; kk < 4; kk++) {
            const int c0 = kbase + 16 * kk + 2 * tig;
#pragma unroll
            for (int h_ = 0; h_ < 4; h_++) {
                const int rr = ra + ((h_ & 1) ? 8 : 0);
                const int cc = c0 + ((h_ & 2) ? 8 : 0);
                Ax[kk][h_] = h2u(attn_W[rr * 128 + cc], attn_W[rr * 128 + cc + 1]);
            }
        }
    }

    // ---- Stage SMEM (enc with XOR swizzle on 16B groups) ----
    {
        const float4* eg = (const float4*)(g_enc_h + (size_t)b0 * (LL * HH));
        float4* es = (float4*)s->encS;
        for (int i = t; i < DNB * LL * 8; i += 512) {
            int nl = i >> 3, g = i & 7;
            int l = nl % LL;
            es[nl * 8 + (g ^ (l & 7))] = eg[i];
        }
    }
    for (int i = t; i < CC * HH; i += 512) {
        int j = i >> 3, k = i & 7;
        s->embW[k][j] = emb_W[i];
        ((float*)s->outW)[i] = out_W[i];
    }
    if (t < 256) s->biasg[t] = g_bias2[t];
    if (t < LL) s->attn_bS[t] = attn_b[t];
    if (t < HH) s->emb_bS[t] = emb_b[t];
    if (t < CC) s->out_bS[t] = out_b[t];
    if (t < DNB * 8) {
        int ba = t >> 3, c = t & 7;
        s->slast[ba][c] = x_enc[(size_t)(b0 + ba) * (LL * CC) + (LL - 1) * CC + c];
    }
    __syncthreads();

    // ---- Per-warp batch state (warp n = batch n) ----
    const int n = wid, j0 = lane, j1 = lane + 32;
    float cst0, cst1, hv0, hv1;
    {
        float2 hA = g_h0_pk[(bp0 + (n >> 1)) * HH + j0];
        float2 hB = g_h0_pk[(bp0 + (n >> 1)) * HH + j1];
        float2 cA = g_c0_pk[(bp0 + (n >> 1)) * HH + j0];
        float2 cB = g_c0_pk[(bp0 + (n >> 1)) * HH + j1];
        hv0 = (n & 1) ? hA.y : hA.x;  hv1 = (n & 1) ? hB.y : hB.x;
        cst0 = (n & 1) ? cA.y : cA.x; cst1 = (n & 1) ? cB.y : cB.x;
    }
    const int kRowOff = (lane & 7) + 8 * ((lane >> 4) & 1);
    const int mHalf   = (lane >> 3) & 1;

    {
        float e0 = fmaxf(s->emb_bS[j0], 0.f), e1 = fmaxf(s->emb_bS[j1], 0.f);
        s->abT[n][j0] = __float2half_rn(e0); s->abT[n][j1] = __float2half_rn(e1);
        s->cbT[n][j0] = __float2half_rn(e0); s->cbT[n][j1] = __float2half_rn(e1);
        s->abT[n][64 + j0] = __float2half_rn(hv0);
        s->abT[n][64 + j1] = __float2half_rn(hv1);
    }
    __syncthreads();

    for (int step = 0; step < TT; step++) {
        // B) attn logits via MMA: 12 warps = 6 m-tiles x 2 K-halves; each warp
        // covers both n-halves. h-half partials go to sg rows 96..191.
        if (wid < 12) {
            const int mw = (wid < 6) ? wid : wid - 6;
            const int kb = (wid < 6) ? 0 : 64;
            const __half* br0 = s->abT[g4];       // batches 0-7
            const __half* br1 = s->abT[8 + g4];   // batches 8-15
            float dA0 = 0.f, dA1 = 0.f, dA2 = 0.f, dA3 = 0.f;
            float dB0 = 0.f, dB1 = 0.f, dB2 = 0.f, dB3 = 0.f;
#pragma unroll
            for (int kk = 0; kk < 4; kk++) {
                const int ko = kb + 16 * kk + 2 * tig;
                unsigned bf0 = *(const unsigned*)&br0[ko];
                unsigned bf1 = *(const unsigned*)&br0[ko + 8];
                mma16816(dA0, dA1, dA2, dA3, Ax[kk][0], Ax[kk][1], Ax[kk][2], Ax[kk][3], bf0, bf1);
                unsigned cf0 = *(const unsigned*)&br1[ko];
                unsigned cf1 = *(const unsigned*)&br1[ko + 8];
                mma16816(dB0, dB1, dB2, dB3, Ax[kk][0], Ax[kk][1], Ax[kk][2], Ax[kk][3], cf0, cf1);
            }
            const int r0 = 16 * mw + g4;
            if (wid < 6) {
                *(__half2*)&s->awl[r0][2 * tig]         = __floats2half2_rn(dA0, dA1);
                *(__half2*)&s->awl[r0 + 8][2 * tig]     = __floats2half2_rn(dA2, dA3);
                *(__half2*)&s->awl[r0][8 + 2 * tig]     = __floats2half2_rn(dB0, dB1);
                *(__half2*)&s->awl[r0 + 8][8 + 2 * tig] = __floats2half2_rn(dB2, dB3);
            } else {
                *(__half2*)&s->sg[96 + r0][2 * tig]         = __floats2half2_rn(dA0, dA1);
                *(__half2*)&s->sg[96 + r0 + 8][2 * tig]     = __floats2half2_rn(dA2, dA3);
                *(__half2*)&s->sg[96 + r0][8 + 2 * tig]     = __floats2half2_rn(dB0, dB1);
                *(__half2*)&s->sg[96 + r0 + 8][8 + 2 * tig] = __floats2half2_rn(dB2, dB3);
            }
        }
        __syncthreads();

        // CD) exp (no max-sub; sum of two k-half partials) + ctx MMA,
        // 16 accumulators, sum-reduce overlapping MMA drain.
        {
            float z0 = __half2float(s->awl[lane][n])      + __half2float(s->sg[96 + lane][n])      + s->attn_bS[lane];
            float z1 = __half2float(s->awl[lane + 32][n]) + __half2float(s->sg[96 + lane + 32][n]) + s->attn_bS[lane + 32];
            float z2 = __half2float(s->awl[lane + 64][n]) + __half2float(s->sg[96 + lane + 64][n]) + s->attn_bS[lane + 64];
            float e0 = __expf(z0), e1 = __expf(z1), e2 = __expf(z2);

            float D[4][4];
#pragma unroll
            for (int jt = 0; jt < 4; jt++) { D[jt][0] = D[jt][1] = D[jt][2] = D[jt][3] = 0.f; }
            const __half* er = s->encS[n];
#pragma unroll
            for (int kt = 0; kt < 6; kt++) {
                float wsrc = (kt < 2) ? e0 : (kt < 4) ? e1 : e2;
                int sb = (kt & 1) * 16 + 2 * tig;
                float vA = __shfl_sync(0xffffffffu, wsrc, sb);
                float vB = __shfl_sync(0xffffffffu, wsrc, sb + 1);
                float vC = __shfl_sync(0xffffffffu, wsrc, sb + 8);
                float vD = __shfl_sync(0xffffffffu, wsrc, sb + 9);
                unsigned bf0 = (g4 == 0) ? h2u(vA, vB) : 0u;
                unsigned bf1 = (g4 == 0) ? h2u(vC, vD) : 0u;
                const int kRow = 16 * kt + kRowOff;
#pragma unroll
                for (int jt = 0; jt < 4; jt++) {
                    const int mGroup = 2 * jt + mHalf;
                    unsigned addr = s2u(&er[kRow * HH + ((mGroup ^ (kRow & 7)) << 3)]);
                    unsigned a0, a1, a2, a3;
                    ldsm4t(a0, a1, a2, a3, addr);
                    mma16816(D[jt][0], D[jt][1], D[jt][2], D[jt][3],
                             a0, a1, a2, a3, bf0, bf1);
                }
            }
            float sum = e0 + e1 + e2;
#pragma unroll
            for (int o = 16; o; o >>= 1) sum += __shfl_xor_sync(0xffffffffu, sum, o);
            float inv = 1.0f / sum;
            if (tig == 0) {
#pragma unroll
                for (int jt = 0; jt < 4; jt++) {
                    s->cbT[n][64 + 16 * jt + g4]     = __float2half_rn(D[jt][0] * inv);
                    s->cbT[n][64 + 16 * jt + g4 + 8] = __float2half_rn(D[jt][2] * inv);
                }
            }
        }
        __syncthreads();

        // F) fused gates: 8 kt from cbT=[emb;ctx] via Wfused + 4 kt from abT-h via Whh
        {
            const __half* cb0p = s->cbT[g4];
            const __half* cb1p = s->cbT[8 + g4];
            const __half* ab0p = s->abT[g4];
            const __half* ab1p = s->abT[8 + g4];
            float gd0[4] = {0, 0, 0, 0}, gd1[4] = {0, 0, 0, 0};
#pragma unroll
            for (int kt = 0; kt < 8; kt++) {
                unsigned a0f = *(const unsigned*)&cb0p[16 * kt + 2 * tig];
                unsigned a1f = *(const unsigned*)&cb0p[16 * kt + 2 * tig + 8];
                mma16816(gd0[0], gd0[1], gd0[2], gd0[3], Ag[kt][0], Ag[kt][1], Ag[kt][2], Ag[kt][3], a0f, a1f);
                unsigned b0f = *(const unsigned*)&cb1p[16 * kt + 2 * tig];
                unsigned b1f = *(const unsigned*)&cb1p[16 * kt + 2 * tig + 8];
                mma16816(gd1[0], gd1[1], gd1[2], gd1[3], Ag[kt][0], Ag[kt][1], Ag[kt][2], Ag[kt][3], b0f, b1f);
            }
#pragma unroll
            for (int kt = 8; kt < 12; kt++) {
                const int co = 64 + 16 * (kt - 8) + 2 * tig;
                unsigned a0f = *(const unsigned*)&ab0p[co];
                unsigned a1f = *(const unsigned*)&ab0p[co + 8];
                mma16816(gd0[0], gd0[1], gd0[2], gd0[3], Ag[kt][0], Ag[kt][1], Ag[kt][2], Ag[kt][3], a0f, a1f);
                unsigned b0f = *(const unsigned*)&ab1p[co];
                unsigned b1f = *(const unsigned*)&ab1p[co + 8];
                mma16816(gd1[0], gd1[1], gd1[2], gd1[3], Ag[kt][0], Ag[kt][1], Ag[kt][2], Ag[kt][3], b0f, b1f);
            }
            const int r0 = 16 * wid + g4;
            *(__half2*)&s->sg[r0][2 * tig]         = __floats2half2_rn(gd0[0], gd0[1]);
            *(__half2*)&s->sg[r0 + 8][2 * tig]     = __floats2half2_rn(gd0[2], gd0[3]);
            *(__half2*)&s->sg[r0][8 + 2 * tig]     = __floats2half2_rn(gd1[0], gd1[1]);
            *(__half2*)&s->sg[r0 + 8][8 + 2 * tig] = __floats2half2_rn(gd1[2], gd1[3]);
        }
        __syncthreads();

        // A) cell + pred + y + next emb (warp n = batch n)
        {
            float gi0 = __half2float(s->sg[j0][n])       + s->biasg[j0];
            float gi1 = __half2float(s->sg[j1][n])       + s->biasg[j1];
            float gf0 = __half2float(s->sg[64 + j0][n])  + s->biasg[64 + j0];
            float gf1 = __half2float(s->sg[64 + j1][n])  + s->biasg[64 + j1];
            float gg0 = __half2float(s->sg[128 + j0][n]) + s->biasg[128 + j0];
            float gg1 = __half2float(s->sg[128 + j1][n]) + s->biasg[128 + j1];
            float go0 = __half2float(s->sg[192 + j0][n]) + s->biasg[192 + j0];
            float go1 = __half2float(s->sg[192 + j1][n]) + s->biasg[192 + j1];
            float i0 = sigt(gi0), i1 = sigt(gi1);
            float f0 = sigt(gf0), f1 = sigt(gf1);
            float tg0 = tanha(gg0), tg1 = tanha(gg1);
            float o0 = sigt(go0), o1 = sigt(go1);
            cst0 = fmaf(f0, cst0, i0 * tg0);
            cst1 = fmaf(f1, cst1, i1 * tg1);
            hv0 = o0 * tanha(cst0);
            hv1 = o1 * tanha(cst1);

            float pc[8];
#pragma unroll
            for (int c = 0; c < 8; c++)
                pc[c] = fmaf(s->outW[c][j0], hv0, s->outW[c][j1] * hv1);
#pragma unroll
            for (int o = 16; o; o >>= 1) {
#pragma unroll
                for (int c = 0; c < 8; c++) pc[c] += __shfl_xor_sync(0xffffffffu, pc[c], o);
            }
#pragma unroll
            for (int c = 0; c < 8; c++) pc[c] += s->out_bS[c];

            if (lane == 0) {
                float4 v0 = *(const float4*)&s->slast[n][0];
                float4 v1 = *(const float4*)&s->slast[n][4];
                float* yp = y + ((size_t)(b0 + n) * TT + step) * CC;
                *(float4*)yp       = make_float4(pc[0] + v0.x, pc[1] + v0.y, pc[2] + v0.z, pc[3] + v0.w);
                *(float4*)(yp + 4) = make_float4(pc[4] + v1.x, pc[5] + v1.y, pc[6] + v1.z, pc[7] + v1.w);
            }

            float e0 = s->emb_bS[j0], e1 = s->emb_bS[j1];
#pragma unroll
            for (int c = 0; c < 8; c++) {
                e0 = fmaf(s->embW[c][j0], pc[c], e0);
                e1 = fmaf(s->embW[c][j1], pc[c], e1);
            }
            e0 = fmaxf(e0, 0.f); e1 = fmaxf(e1, 0.f);
            s->abT[n][j0] = __float2half_rn(e0); s->abT[n][j1] = __float2half_rn(e1);
            s->cbT[n][j0] = __float2half_rn(e0); s->cbT[n][j1] = __float2half_rn(e1);
            s->abT[n][64 + j0] = __float2half_rn(hv0);
            s->abT[n][64 + j1] = __float2half_rn(hv1);
        }
        __syncthreads();
    }
}

extern "C" void kernel_launch(void* const* d_in, const int* in_sizes, int n_in,
                              void* d_out, int out_size)
{
    const float* x_enc   = (const float*)d_in[0];
    const float* enc_Wih = (const float*)d_in[4];
    const float* enc_Whh = (const float*)d_in[5];
    const float* enc_bih = (const float*)d_in[6];
    const float* enc_bhh = (const float*)d_in[7];
    const float* emb_W   = (const float*)d_in[8];
    const float* emb_b   = (const float*)d_in[9];
    const float* attn_W  = (const float*)d_in[10];
    const float* attn_b  = (const float*)d_in[11];
    const float* comb_W  = (const float*)d_in[12];
    const float* comb_b  = (const float*)d_in[13];
    const float* dec_Wih = (const float*)d_in[14];
    const float* dec_Whh = (const float*)d_in[15];
    const float* dec_bih = (const float*)d_in[16];
    const float* dec_bhh = (const float*)d_in[17];
    const float* out_W   = (const float*)d_in[18];
    const float* out_b   = (const float*)d_in[19];
    float* y = (float*)d_out;

    cudaFuncSetAttribute(enc_kernel, cudaFuncAttributeMaxDynamicSharedMemorySize,
                         (int)sizeof(EncSmem));
    cudaFuncSetAttribute(dec_kernel, cudaFuncAttributeMaxDynamicSharedMemorySize,
                         (int)sizeof(DecSmem));

    enc_kernel<<<BB / ENB, 256, sizeof(EncSmem)>>>(x_enc, enc_Wih, enc_Whh, enc_bih, enc_bhh,
                                                   dec_Wih, comb_W, dec_bih, dec_bhh, comb_b);
    dec_kernel<<<BB / DNB, 512, sizeof(DecSmem)>>>(x_enc, emb_W, emb_b, attn_W, attn_b,
                                                   dec_Whh, out_W, out_b, y);
}